// round 10
// baseline (speedup 1.0000x reference)
#include <cuda_runtime.h>
#include <cuda_bf16.h>
#include <stdint.h>

#define NROWS 65536
#define XD    362
#define NA    3
#define TILE  128
#define NT    (NROWS / TILE)   // 512
#define NTHR  256

#define P_H1  120   // bf16 pitch (conflict-free ldmatrix)
#define P_W2  120
#define P_W3  408

#define PTHR1      1024
#define RPB        32
#define PREP_BLKS  (NROWS / RPB)      // 2048
#define WPREP_BLKS 8

// ---------------- device scratch (statically zero at load) ----------------
__device__ float  g_buck[(size_t)NA * NROWS * 12];  // bucketed att(6)+delta(6)
__device__ int    g_cnt[NA];                        // k_fin resets
__device__ double g_acc;                            // k_fin resets
__device__ uint4  g_w2t_u4[(size_t)NA * 400 * 14];  // [a][n<400][k<112] bf16
__device__ uint4  g_w3t_u4[(size_t)NA * 104 * 50];  // [a][n<104][k<400] bf16

// ---------------- helpers ----------------
__device__ __forceinline__ uint32_t smem_u32(const void* p) {
    uint32_t a;
    asm("{ .reg .u64 t; cvta.to.shared.u64 t, %1; cvt.u32.u64 %0, t; }" : "=r"(a) : "l"(p));
    return a;
}
#define CVT_BF16X2(res, lo, hi) \
    asm("cvt.rn.bf16x2.f32 %0, %1, %2;" : "=r"(res) : "f"(hi), "f"(lo))

__device__ __forceinline__ void ldmA(uint32_t* a, uint32_t addr) {
    asm volatile("ldmatrix.sync.aligned.m8n8.x4.shared.b16 {%0,%1,%2,%3}, [%4];"
        : "=r"(a[0]), "=r"(a[1]), "=r"(a[2]), "=r"(a[3]) : "r"(addr));
}
__device__ __forceinline__ void ldmB2(uint32_t& b0, uint32_t& b1, uint32_t addr) {
    asm volatile("ldmatrix.sync.aligned.m8n8.x2.shared.b16 {%0,%1}, [%2];"
        : "=r"(b0), "=r"(b1) : "r"(addr));
}
__device__ __forceinline__ void ldmB4(uint32_t* b, uint32_t addr) {
    asm volatile("ldmatrix.sync.aligned.m8n8.x4.shared.b16 {%0,%1,%2,%3}, [%4];"
        : "=r"(b[0]), "=r"(b[1]), "=r"(b[2]), "=r"(b[3]) : "r"(addr));
}
__device__ __forceinline__ void mma16816(float* c, const uint32_t* a, uint32_t b0, uint32_t b1) {
    asm volatile("mma.sync.aligned.m16n8k16.row.col.f32.bf16.bf16.f32 "
        "{%0,%1,%2,%3}, {%4,%5,%6,%7}, {%8,%9}, {%0,%1,%2,%3};"
        : "+f"(c[0]), "+f"(c[1]), "+f"(c[2]), "+f"(c[3])
        : "r"(a[0]), "r"(a[1]), "r"(a[2]), "r"(a[3]), "r"(b0), "r"(b1));
}
__device__ __forceinline__ uint32_t addrA(uint32_t base, int lane, int m0, int k0, int P) {
    int j = lane >> 3;
    int row = m0 + ((j & 1) << 3) + (lane & 7);
    int col = k0 + ((j >> 1) << 3);
    return base + (uint32_t)(row * P + col) * 2u;
}
__device__ __forceinline__ uint32_t addrB2(uint32_t base, int lane, int n0, int k0, int P) {
    int l = lane & 15;
    int row = n0 + (l & 7);
    int col = k0 + ((l >> 3) << 3);
    return base + (uint32_t)(row * P + col) * 2u;
}
__device__ __forceinline__ uint32_t addrB4(uint32_t base, int lane, int n0, int k0, int P) {
    int row = n0 + ((lane >> 4) << 3) + (lane & 7);
    int col = k0 + (((lane >> 3) & 1) << 3);
    return base + (uint32_t)(row * P + col) * 2u;
}

// ---------------- prep: scan + register-gather + hierarchical scatter ----------------
__global__ __launch_bounds__(PTHR1)
void k_prep(const float* __restrict__ x, const float* __restrict__ nx,
            const int* __restrict__ act,
            const float* __restrict__ W2, const float* __restrict__ W3) {
    if (blockIdx.x >= PREP_BLKS) {   // weight transpose blocks
        int i = (blockIdx.x - PREP_BLKS) * PTHR1 + threadIdx.x;
        int stride = WPREP_BLKS * PTHR1;
        __nv_bfloat16* w2t = (__nv_bfloat16*)g_w2t_u4;
        __nv_bfloat16* w3t = (__nv_bfloat16*)g_w3t_u4;
        for (int t = i; t < NA * 400 * 112; t += stride) {
            int k = t % 112, n = (t / 112) % 400, a = t / (112 * 400);
            float v = (k < 100) ? W2[(size_t)a * 40000 + k * 400 + n] : 0.f;
            w2t[t] = __float2bfloat16(v);
        }
        for (int t = i; t < NA * 104 * 400; t += stride) {
            int k = t % 400, n = (t / 400) % 104, a = t / (400 * 104);
            float v = (n < 100) ? W3[(size_t)a * 40000 + k * 100 + n] : 0.f;
            w3t[t] = __float2bfloat16(v);
        }
        return;
    }

    __shared__ int scnt[NA], sbase[NA];
    const int wid  = threadIdx.x >> 5;
    const int lane = threadIdx.x & 31;
    if (threadIdx.x < NA) scnt[threadIdx.x] = 0;
    __syncthreads();

    const int row = blockIdx.x * RPB + wid;
    const int a   = act[row];                       // early independent load
    const float* xr = x + (size_t)row * XD;

    // window [0,256): 4 independent float2 loads per lane
    float2 v0 = *(const float2*)(xr + 2 * lane);
    float2 v1 = *(const float2*)(xr + 2 * lane + 64);
    float2 v2 = *(const float2*)(xr + 2 * lane + 128);
    float2 v3 = *(const float2*)(xr + 2 * lane + 192);
    int found = 0x7fffffff;
    if (v3.y == 10.0f) found = 2 * lane + 193;
    if (v3.x == 10.0f) found = 2 * lane + 192;
    if (v2.y == 10.0f) found = 2 * lane + 129;
    if (v2.x == 10.0f) found = 2 * lane + 128;
    if (v1.y == 10.0f) found = 2 * lane + 65;
    if (v1.x == 10.0f) found = 2 * lane + 64;
    if (v0.y == 10.0f) found = 2 * lane + 1;
    if (v0.x == 10.0f) found = 2 * lane;
    if (!__ballot_sync(0xffffffffu, found != 0x7fffffff)) {
        int i2 = 256 + 2 * lane;
        float2 v4 = *(const float2*)(xr + i2);
        float2 v5 = make_float2(0.f, 0.f);
        if (i2 + 65 < XD) v5 = *(const float2*)(xr + i2 + 64);
        if (v5.y == 10.0f) found = i2 + 65;
        if (v5.x == 10.0f) found = i2 + 64;
        if (v4.y == 10.0f) found = i2 + 1;
        if (v4.x == 10.0f) found = i2;
    }
    #pragma unroll
    for (int off = 16; off; off >>= 1)
        found = min(found, __shfl_xor_sync(0xffffffffu, found, off));
    int p = found;
    if (p < 19 || p >= XD - 19) p = 20;

    int rank = 0;
    if (lane == 0) rank = atomicAdd(&scnt[a], 1);
    rank = __shfl_sync(0xffffffffu, rank, 0);
    __syncthreads();
    if (threadIdx.x < NA)
        sbase[threadIdx.x] = atomicAdd(&g_cnt[threadIdx.x], scnt[threadIdx.x]);
    __syncthreads();
    const int slot = sbase[a] + rank;

    // gather index per lane (lanes 0..5)
    int idx = 0;
    if      (lane == 1) idx = p;
    else if (lane == 2) idx = p - 19;
    else if (lane == 3) idx = p + 19;
    else if (lane == 4) idx = p - 1;
    else if (lane == 5) idx = p + 1;

    // att from scan registers via shuffle (window hit); reload otherwise
    int sx = (idx >> 1) & 31;
    float w0x = __shfl_sync(0xffffffffu, v0.x, sx), w0y = __shfl_sync(0xffffffffu, v0.y, sx);
    float w1x = __shfl_sync(0xffffffffu, v1.x, sx), w1y = __shfl_sync(0xffffffffu, v1.y, sx);
    float w2x = __shfl_sync(0xffffffffu, v2.x, sx), w2y = __shfl_sync(0xffffffffu, v2.y, sx);
    float w3x = __shfl_sync(0xffffffffu, v3.x, sx), w3y = __shfl_sync(0xffffffffu, v3.y, sx);
    if (lane < 6) {
        int seg = idx >> 6, half = idx & 1;
        float av = (seg == 0) ? (half ? w0y : w0x)
                 : (seg == 1) ? (half ? w1y : w1x)
                 : (seg == 2) ? (half ? w2y : w2x)
                 :              (half ? w3y : w3x);
        if (idx > 255) av = xr[idx];
        float nv = nx[(size_t)row * XD + idx];
        float* dst = g_buck + ((size_t)a * NROWS + slot) * 12;
        dst[lane]     = av;
        dst[6 + lane] = nv - av;
    }
}

// ---------------- smem layout (bytes) ----------------
#define O_H1   0u         // 128*120*2 = 30720
#define O_W2B  30720u     // 400*240 = 96000
#define O_W3B  126720u    // 104*816 = 84864
#define O_SX   211584u    // 128*6*4 = 3072
#define O_SD   214656u    // 3072
#define O_W1   217728u    // 2400
#define O_B1   220128u    // 400
#define O_B2   220528u    // 1600
#define O_B3   222128u    // 400
#define O_W4   222528u    // 2400
#define O_B4   224928u    // 32
#define O_RED  224960u    // 32
#define SMEM_REQ 224992u

// ---------------- fused MLP tile kernel (full weights resident) ----------------
__global__ __launch_bounds__(NTHR, 1)
void k_mlp(const float* __restrict__ W1, const float* __restrict__ b1,
           const float* __restrict__ b2, const float* __restrict__ b3,
           const float* __restrict__ W4, const float* __restrict__ b4) {
    extern __shared__ char sb[];
    const uint32_t sb32 = smem_u32(sb);

    const int a    = blockIdx.x / NT;
    const int t    = blockIdx.x % NT;
    const int cnt  = g_cnt[a];
    const int row0 = t * TILE;
    if (row0 >= cnt) return;
    const int nrows = min(TILE, cnt - row0);
    const int tid   = threadIdx.x;
    const int wid   = tid >> 5;
    const int lane  = tid & 31;
    const int m0    = wid * 16;

    float* sX  = (float*)(sb + O_SX);
    float* sD  = (float*)(sb + O_SD);
    float* sW1 = (float*)(sb + O_W1);
    float* sB1 = (float*)(sb + O_B1);
    float* sB2 = (float*)(sb + O_B2);
    float* sB3 = (float*)(sb + O_B3);
    float* sW4 = (float*)(sb + O_W4);
    float* sB4 = (float*)(sb + O_B4);
    float* sRed = (float*)(sb + O_RED);

    {   // stage inputs + ALL weights (once)
        const float* gB = g_buck + ((size_t)a * NROWS + row0) * 12;
        for (int i = tid; i < TILE * 12; i += NTHR) {
            int r = i / 12, j = i - 12 * r;
            float v = gB[i];
            if (j < 6) sX[r * 6 + j] = v; else sD[r * 6 + j - 6] = v;
        }
        const uint4* w2s = g_w2t_u4 + (size_t)a * 400 * 14;
        for (int i = tid; i < 400 * 14; i += NTHR) {
            int n = i / 14, q = i - n * 14;
            *(uint4*)(sb + O_W2B + n * (P_W2 * 2) + q * 16) = w2s[i];
        }
        const uint4* w3s = g_w3t_u4 + (size_t)a * 104 * 50;
        for (int i = tid; i < 104 * 50; i += NTHR) {
            int n = i / 50, q = i - n * 50;
            *(uint4*)(sb + O_W3B + n * (P_W3 * 2) + q * 16) = w3s[i];
        }
        for (int i = tid; i < 600; i += NTHR) sW1[i] = W1[a * 600 + i];
        for (int i = tid; i < 600; i += NTHR) sW4[i] = W4[a * 600 + i];
        for (int i = tid; i < 400; i += NTHR) sB2[i] = b2[a * 400 + i];
        if (tid < 100) sB1[tid] = b1[a * 100 + tid];
        if (tid < 100) sB3[tid] = b3[a * 100 + tid];
        if (tid < 8)   sB4[tid] = (tid < 6) ? b4[a * 6 + tid] : 0.f;
    }
    __syncthreads();

    // ---- layer 1 (fp32) -> H1 bf16 [128][120], zero-pad k 100..119 ----
    {
        const int r = tid & 127;
        const int h = tid >> 7;
        const float* xr = sX + r * 6;
        #pragma unroll
        for (int c = 0; c < 50; c += 2) {
            int j = h * 50 + c;
            float s0 = sB1[j], s1 = sB1[j + 1];
            #pragma unroll
            for (int k = 0; k < 6; k++) {
                s0 = fmaf(xr[k], sW1[k * 100 + j], s0);
                s1 = fmaf(xr[k], sW1[k * 100 + j + 1], s1);
            }
            uint32_t pk; CVT_BF16X2(pk, fmaxf(s0, 0.f), fmaxf(s1, 0.f));
            *(uint32_t*)(sb + O_H1 + (r * P_H1 + j) * 2) = pk;
        }
        if (h == 1) {
            #pragma unroll
            for (int j = 100; j < 120; j += 2)
                *(uint32_t*)(sb + O_H1 + (r * P_H1 + j) * 2) = 0u;
        }
    }
    __syncthreads();

    // cache layer-2 A fragments
    uint32_t a2f[7][4];
    #pragma unroll
    for (int ks = 0; ks < 7; ks++)
        ldmA(a2f[ks], addrA(sb32 + O_H1, lane, m0, ks * 16, P_H1));

    float acc[13][4];
    #pragma unroll
    for (int nt = 0; nt < 13; nt++)
        #pragma unroll
        for (int j = 0; j < 4; j++) acc[nt][j] = 0.f;

    const uint32_t w2b = sb32 + O_W2B;
    const uint32_t w3b = sb32 + O_W3B;

    // ---- fused layers 2+3: 25 kb iterations, no barriers, H2 in registers ----
    for (int kb = 0; kb < 25; kb++) {
        float c0v[4] = {0.f, 0.f, 0.f, 0.f};
        float c1v[4] = {0.f, 0.f, 0.f, 0.f};
        #pragma unroll
        for (int ks = 0; ks < 7; ks++) {
            uint32_t bb[4];
            ldmB4(bb, addrB4(w2b, lane, kb * 16, ks * 16, P_W2));
            mma16816(c0v, a2f[ks], bb[0], bb[1]);
            mma16816(c1v, a2f[ks], bb[2], bb[3]);
        }
        const int cA = kb * 16 + 2 * (lane & 3);
        uint32_t afr[4];
        {
            float g0 = sB2[cA],     g1 = sB2[cA + 1];
            float g2 = sB2[cA + 8], g3 = sB2[cA + 9];
            CVT_BF16X2(afr[0], fmaxf(c0v[0] + g0, 0.f), fmaxf(c0v[1] + g1, 0.f));
            CVT_BF16X2(afr[1], fmaxf(c0v[2] + g0, 0.f), fmaxf(c0v[3] + g1, 0.f));
            CVT_BF16X2(afr[2], fmaxf(c1v[0] + g2, 0.f), fmaxf(c1v[1] + g3, 0.f));
            CVT_BF16X2(afr[3], fmaxf(c1v[2] + g2, 0.f), fmaxf(c1v[3] + g3, 0.f));
        }
        #pragma unroll
        for (int p = 0; p < 6; p++) {
            uint32_t bb[4];
            ldmB4(bb, addrB4(w3b, lane, p * 16, kb * 16, P_W3));
            mma16816(acc[2 * p],     afr, bb[0], bb[1]);
            mma16816(acc[2 * p + 1], afr, bb[2], bb[3]);
        }
        {
            uint32_t b0, b1v;
            ldmB2(b0, b1v, addrB2(w3b, lane, 96, kb * 16, P_W3));
            mma16816(acc[12], afr, b0, b1v);
        }
    }

    // ---- layer 4 directly from fragments + quad reduction + MSE ----
    float psA[6] = {0.f, 0.f, 0.f, 0.f, 0.f, 0.f};
    float psB[6] = {0.f, 0.f, 0.f, 0.f, 0.f, 0.f};
    const int q = lane & 3;
    #pragma unroll
    for (int nt = 0; nt < 13; nt++) {
        int c = nt * 8 + 2 * q;
        if (c < 100) {
            float h0A = fmaxf(acc[nt][0] + sB3[c],     0.f);
            float h1A = fmaxf(acc[nt][1] + sB3[c + 1], 0.f);
            float h0B = fmaxf(acc[nt][2] + sB3[c],     0.f);
            float h1B = fmaxf(acc[nt][3] + sB3[c + 1], 0.f);
            #pragma unroll
            for (int c6 = 0; c6 < 6; c6++) {
                float w0 = sW4[c * 6 + c6], w1 = sW4[(c + 1) * 6 + c6];
                psA[c6] = fmaf(h0A, w0, fmaf(h1A, w1, psA[c6]));
                psB[c6] = fmaf(h0B, w0, fmaf(h1B, w1, psB[c6]));
            }
        }
    }
    #pragma unroll
    for (int off = 1; off <= 2; off <<= 1)
        #pragma unroll
        for (int c6 = 0; c6 < 6; c6++) {
            psA[c6] += __shfl_xor_sync(0xffffffffu, psA[c6], off);
            psB[c6] += __shfl_xor_sync(0xffffffffu, psB[c6], off);
        }
    float local = 0.f;
    if (q == 0) {
        int rA = m0 + (lane >> 2), rB = rA + 8;
        #pragma unroll
        for (int c6 = 0; c6 < 6; c6++) {
            if (rA < nrows) { float d = psA[c6] + sB4[c6] - sD[rA * 6 + c6]; local += d * d; }
            if (rB < nrows) { float d = psB[c6] + sB4[c6] - sD[rB * 6 + c6]; local += d * d; }
        }
    }
    #pragma unroll
    for (int off = 16; off; off >>= 1) local += __shfl_xor_sync(0xffffffffu, local, off);
    if (lane == 0) sRed[wid] = local;
    __syncthreads();
    if (tid == 0) {
        float s = 0.f;
        #pragma unroll
        for (int i = 0; i < 8; i++) s += sRed[i];
        atomicAdd(&g_acc, (double)s);
    }
}

__global__ void k_fin(float* out, int n) {
    double acc = g_acc;
    float v = (float)(acc / ((double)NROWS * 6.0));
    for (int i = threadIdx.x; i < n; i += blockDim.x) out[i] = v;
    __syncthreads();
    if (threadIdx.x < NA) g_cnt[threadIdx.x] = 0;
    if (threadIdx.x == NA) g_acc = 0.0;
}

extern "C" void kernel_launch(void* const* d_in, const int* in_sizes, int n_in,
                              void* d_out, int out_size) {
    const float* x  = (const float*)d_in[0];
    const float* nx = (const float*)d_in[1];
    const int*   ac = (const int*)d_in[2];
    const float* W1 = (const float*)d_in[3];
    const float* b1 = (const float*)d_in[4];
    const float* W2 = (const float*)d_in[5];
    const float* b2 = (const float*)d_in[6];
    const float* W3 = (const float*)d_in[7];
    const float* b3 = (const float*)d_in[8];
    const float* W4 = (const float*)d_in[9];
    const float* b4 = (const float*)d_in[10];

    cudaFuncSetAttribute(k_mlp, cudaFuncAttributeMaxDynamicSharedMemorySize, (int)SMEM_REQ);

    k_prep<<<PREP_BLKS + WPREP_BLKS, PTHR1>>>(x, nx, ac, W2, W3);
    k_mlp<<<NA * NT, NTHR, SMEM_REQ>>>(W1, b1, b2, b3, W4, b4);
    k_fin<<<1, 64>>>((float*)d_out, out_size);
}

// round 11
// speedup vs baseline: 1.1835x; 1.1835x over previous
#include <cuda_runtime.h>
#include <cuda_bf16.h>
#include <stdint.h>

#define NROWS 65536
#define XD    362
#define NA    3
#define TILE  256
#define NT    (NROWS / TILE)   // 256
#define NTHR  512

#define P_H1  120   // bf16 pitch, conflict-free ldmatrix
#define P_W2  120
#define P_W3  216

#define PTHR1      1024
#define RPB        32
#define PREP_BLKS  (NROWS / RPB)      // 2048
#define WPREP_BLKS 8

// ---------------- device scratch (statically zero at load) ----------------
__device__ float  g_buck[(size_t)NA * NROWS * 12];  // bucketed att(6)+delta(6)
__device__ int    g_cnt[NA];                        // k_fin resets
__device__ double g_acc;                            // k_fin resets
__device__ uint4  g_w2t_u4[(size_t)NA * 400 * 14];  // [a][n<400][k<112] bf16
__device__ uint4  g_w3t_u4[(size_t)NA * 104 * 50];  // [a][n<104][k<400] bf16

// ---------------- helpers ----------------
__device__ __forceinline__ uint32_t smem_u32(const void* p) {
    uint32_t a;
    asm("{ .reg .u64 t; cvta.to.shared.u64 t, %1; cvt.u32.u64 %0, t; }" : "=r"(a) : "l"(p));
    return a;
}
#define CVT_BF16X2(res, lo, hi) \
    asm("cvt.rn.bf16x2.f32 %0, %1, %2;" : "=r"(res) : "f"(hi), "f"(lo))

__device__ __forceinline__ void ldmA(uint32_t* a, uint32_t addr) {
    asm volatile("ldmatrix.sync.aligned.m8n8.x4.shared.b16 {%0,%1,%2,%3}, [%4];"
        : "=r"(a[0]), "=r"(a[1]), "=r"(a[2]), "=r"(a[3]) : "r"(addr));
}
__device__ __forceinline__ void ldmB2(uint32_t& b0, uint32_t& b1, uint32_t addr) {
    asm volatile("ldmatrix.sync.aligned.m8n8.x2.shared.b16 {%0,%1}, [%2];"
        : "=r"(b0), "=r"(b1) : "r"(addr));
}
__device__ __forceinline__ void ldmB4(uint32_t* b, uint32_t addr) {
    asm volatile("ldmatrix.sync.aligned.m8n8.x4.shared.b16 {%0,%1,%2,%3}, [%4];"
        : "=r"(b[0]), "=r"(b[1]), "=r"(b[2]), "=r"(b[3]) : "r"(addr));
}
__device__ __forceinline__ void mma16816(float* c, const uint32_t* a, uint32_t b0, uint32_t b1) {
    asm volatile("mma.sync.aligned.m16n8k16.row.col.f32.bf16.bf16.f32 "
        "{%0,%1,%2,%3}, {%4,%5,%6,%7}, {%8,%9}, {%0,%1,%2,%3};"
        : "+f"(c[0]), "+f"(c[1]), "+f"(c[2]), "+f"(c[3])
        : "r"(a[0]), "r"(a[1]), "r"(a[2]), "r"(a[3]), "r"(b0), "r"(b1));
}
__device__ __forceinline__ uint32_t addrA(uint32_t base, int lane, int m0, int k0, int P) {
    int j = lane >> 3;
    int row = m0 + ((j & 1) << 3) + (lane & 7);
    int col = k0 + ((j >> 1) << 3);
    return base + (uint32_t)(row * P + col) * 2u;
}
__device__ __forceinline__ uint32_t addrB2(uint32_t base, int lane, int n0, int k0, int P) {
    int l = lane & 15;
    int row = n0 + (l & 7);
    int col = k0 + ((l >> 3) << 3);
    return base + (uint32_t)(row * P + col) * 2u;
}
__device__ __forceinline__ uint32_t addrB4(uint32_t base, int lane, int n0, int k0, int P) {
    int row = n0 + ((lane >> 4) << 3) + (lane & 7);
    int col = k0 + (((lane >> 3) & 1) << 3);
    return base + (uint32_t)(row * P + col) * 2u;
}

// ---------------- prep: single-phase scan + hierarchical bucket-scatter ----------------
__global__ __launch_bounds__(PTHR1)
void k_prep(const float* __restrict__ x, const float* __restrict__ nx,
            const int* __restrict__ act,
            const float* __restrict__ W2, const float* __restrict__ W3) {
    if (blockIdx.x >= PREP_BLKS) {   // weight transpose blocks
        int i = (blockIdx.x - PREP_BLKS) * PTHR1 + threadIdx.x;
        int stride = WPREP_BLKS * PTHR1;
        __nv_bfloat16* w2t = (__nv_bfloat16*)g_w2t_u4;
        __nv_bfloat16* w3t = (__nv_bfloat16*)g_w3t_u4;
        for (int t = i; t < NA * 400 * 112; t += stride) {
            int k = t % 112, n = (t / 112) % 400, a = t / (112 * 400);
            float v = (k < 100) ? W2[(size_t)a * 40000 + k * 400 + n] : 0.f;
            w2t[t] = __float2bfloat16(v);
        }
        for (int t = i; t < NA * 104 * 400; t += stride) {
            int k = t % 400, n = (t / 400) % 104, a = t / (400 * 104);
            float v = (n < 100) ? W3[(size_t)a * 40000 + k * 100 + n] : 0.f;
            w3t[t] = __float2bfloat16(v);
        }
        return;
    }

    __shared__ int scnt[NA], sbase[NA];
    const int wid  = threadIdx.x >> 5;
    const int lane = threadIdx.x & 31;
    if (threadIdx.x < NA) scnt[threadIdx.x] = 0;
    __syncthreads();

    const int row = blockIdx.x * RPB + wid;
    const int a   = act[row];                       // early independent load
    const float* xr = x + (size_t)row * XD;

    // single-phase full-row scan: 6 independent float2 loads (last predicated)
    float2 v0 = *(const float2*)(xr + 2 * lane);
    float2 v1 = *(const float2*)(xr + 2 * lane + 64);
    float2 v2 = *(const float2*)(xr + 2 * lane + 128);
    float2 v3 = *(const float2*)(xr + 2 * lane + 192);
    float2 v4 = *(const float2*)(xr + 2 * lane + 256);
    float2 v5 = make_float2(0.f, 0.f);
    if (lane <= 20) v5 = *(const float2*)(xr + 2 * lane + 320);   // covers [320,362)

    int found = 0x7fffffff;
    if (v5.y == 10.0f) found = 2 * lane + 321;
    if (v5.x == 10.0f) found = 2 * lane + 320;
    if (v4.y == 10.0f) found = 2 * lane + 257;
    if (v4.x == 10.0f) found = 2 * lane + 256;
    if (v3.y == 10.0f) found = 2 * lane + 193;
    if (v3.x == 10.0f) found = 2 * lane + 192;
    if (v2.y == 10.0f) found = 2 * lane + 129;
    if (v2.x == 10.0f) found = 2 * lane + 128;
    if (v1.y == 10.0f) found = 2 * lane + 65;
    if (v1.x == 10.0f) found = 2 * lane + 64;
    if (v0.y == 10.0f) found = 2 * lane + 1;
    if (v0.x == 10.0f) found = 2 * lane;
    #pragma unroll
    for (int off = 16; off; off >>= 1)
        found = min(found, __shfl_xor_sync(0xffffffffu, found, off));
    int p = found;
    if (p < 19 || p >= XD - 19) p = 20;

    int rank = 0;
    if (lane == 0) rank = atomicAdd(&scnt[a], 1);
    rank = __shfl_sync(0xffffffffu, rank, 0);
    __syncthreads();
    if (threadIdx.x < NA)
        sbase[threadIdx.x] = atomicAdd(&g_cnt[threadIdx.x], scnt[threadIdx.x]);
    __syncthreads();
    const int slot = sbase[a] + rank;

    if (lane < 6) {
        int idx = 0;
        if      (lane == 1) idx = p;
        else if (lane == 2) idx = p - 19;
        else if (lane == 3) idx = p + 19;
        else if (lane == 4) idx = p - 1;
        else if (lane == 5) idx = p + 1;
        float av = xr[idx];                          // L1 hit (row just scanned)
        float nv = nx[(size_t)row * XD + idx];
        float* dst = g_buck + ((size_t)a * NROWS + slot) * 12;
        dst[lane]     = av;
        dst[6 + lane] = nv - av;
    }
}

// ---------------- smem layout (bytes) ----------------
#define O_H1   0u         // 256*120*2 = 61440
#define O_W2B  61440u     // 208*240 = 49920
#define O_W3B  111360u    // 104*432 = 44928
#define O_SX   156288u
#define O_SD   162432u
#define O_W1   168576u
#define O_B1   170976u
#define O_B2   171376u
#define O_B3   172976u
#define O_W4   173376u
#define O_B4   175776u
#define O_RED  175808u
#define SMEM_REQ 175872u

__device__ __forceinline__ void stage_w2(char* sb, int a, int c0, int nrow, int tid) {
    const uint4* src = g_w2t_u4 + ((size_t)a * 400 + c0) * 14;
    for (int i = tid; i < nrow * 14; i += NTHR) {
        int n = i / 14, q = i - n * 14;
        *(uint4*)(sb + O_W2B + n * (P_W2 * 2) + q * 16) = src[i];
    }
}
__device__ __forceinline__ void stage_w3(char* sb, int a, int k0, int nk, int tid) {
    const uint4* src = g_w3t_u4 + (size_t)a * 104 * 50 + (k0 >> 3);
    const int nq = nk >> 3;
    for (int i = tid; i < 104 * nq; i += NTHR) {
        int n = i / nq, q = i - n * nq;
        *(uint4*)(sb + O_W3B + n * (P_W3 * 2) + q * 16) = src[n * 50 + q];
    }
}

// ---------------- fused MLP tile kernel (TILE=256, two-half staging) ----------------
__global__ __launch_bounds__(NTHR, 1)
void k_mlp(const float* __restrict__ W1, const float* __restrict__ b1,
           const float* __restrict__ b2, const float* __restrict__ b3,
           const float* __restrict__ W4, const float* __restrict__ b4) {
    extern __shared__ char sb[];
    const uint32_t sb32 = smem_u32(sb);

    const int a    = blockIdx.x / NT;
    const int t    = blockIdx.x % NT;
    const int cnt  = g_cnt[a];
    const int row0 = t * TILE;
    if (row0 >= cnt) return;
    const int nrows = min(TILE, cnt - row0);
    const int tid   = threadIdx.x;
    const int wid   = tid >> 5;
    const int lane  = tid & 31;
    const int m0    = wid * 16;

    float* sX  = (float*)(sb + O_SX);
    float* sD  = (float*)(sb + O_SD);
    float* sW1 = (float*)(sb + O_W1);
    float* sB1 = (float*)(sb + O_B1);
    float* sB2 = (float*)(sb + O_B2);
    float* sB3 = (float*)(sb + O_B3);
    float* sW4 = (float*)(sb + O_W4);
    float* sB4 = (float*)(sb + O_B4);
    float* sRed = (float*)(sb + O_RED);

    {   // stage inputs + small weights + half-0 big-weight slabs
        const float* gB = g_buck + ((size_t)a * NROWS + row0) * 12;
        for (int i = tid; i < TILE * 12; i += NTHR) {
            int r = i / 12, j = i - 12 * r;
            float v = gB[i];
            if (j < 6) sX[r * 6 + j] = v; else sD[r * 6 + j - 6] = v;
        }
        stage_w2(sb, a, 0, 192, tid);
        stage_w3(sb, a, 0, 192, tid);
        for (int i = tid; i < 600; i += NTHR) sW1[i] = W1[a * 600 + i];
        for (int i = tid; i < 600; i += NTHR) sW4[i] = W4[a * 600 + i];
        for (int i = tid; i < 400; i += NTHR) sB2[i] = b2[a * 400 + i];
        if (tid < 100) sB1[tid] = b1[a * 100 + tid];
        if (tid < 100) sB3[tid] = b3[a * 100 + tid];
        if (tid < 8)   sB4[tid] = (tid < 6) ? b4[a * 6 + tid] : 0.f;
    }
    __syncthreads();

    // ---- layer 1 (fp32) -> H1 bf16 [256][120], zero-pad k 100..119 ----
    {
        const int r = tid & 255;
        const int h = tid >> 8;
        const float* xr = sX + r * 6;
        #pragma unroll
        for (int c = 0; c < 50; c += 2) {
            int j = h * 50 + c;
            float s0 = sB1[j], s1 = sB1[j + 1];
            #pragma unroll
            for (int k = 0; k < 6; k++) {
                s0 = fmaf(xr[k], sW1[k * 100 + j], s0);
                s1 = fmaf(xr[k], sW1[k * 100 + j + 1], s1);
            }
            uint32_t pk; CVT_BF16X2(pk, fmaxf(s0, 0.f), fmaxf(s1, 0.f));
            *(uint32_t*)(sb + O_H1 + (r * P_H1 + j) * 2) = pk;
        }
        if (h == 1) {
            #pragma unroll
            for (int j = 100; j < 120; j += 2)
                *(uint32_t*)(sb + O_H1 + (r * P_H1 + j) * 2) = 0u;
        }
    }
    __syncthreads();

    // cache layer-2 A fragments (persist across both halves)
    uint32_t a2f[7][4];
    #pragma unroll
    for (int ks = 0; ks < 7; ks++)
        ldmA(a2f[ks], addrA(sb32 + O_H1, lane, m0, ks * 16, P_H1));

    float acc[13][4];
    #pragma unroll
    for (int nt = 0; nt < 13; nt++)
        #pragma unroll
        for (int j = 0; j < 4; j++) acc[nt][j] = 0.f;

    const uint32_t w2b = sb32 + O_W2B;
    const uint32_t w3b = sb32 + O_W3B;

    // ---- fused layers 2+3 over two K/N halves; H2 stays in registers ----
    #pragma unroll
    for (int half = 0; half < 2; half++) {
        const int c0   = half ? 192 : 0;
        const int kb_s = half ? 12 : 0;
        const int kb_e = half ? 25 : 12;
        if (half) {
            __syncthreads();
            stage_w2(sb, a, c0, 208, tid);
            stage_w3(sb, a, c0, 208, tid);
            __syncthreads();
        }

        for (int kb = kb_s; kb < kb_e; kb++) {
            float c0v[4] = {0.f, 0.f, 0.f, 0.f};
            float c1v[4] = {0.f, 0.f, 0.f, 0.f};
            const int nloc = kb * 16 - c0;
            #pragma unroll
            for (int ks = 0; ks < 7; ks++) {
                uint32_t bb[4];
                ldmB4(bb, addrB4(w2b, lane, nloc, ks * 16, P_W2));
                mma16816(c0v, a2f[ks], bb[0], bb[1]);
                mma16816(c1v, a2f[ks], bb[2], bb[3]);
            }
            const int cA = kb * 16 + 2 * (lane & 3);
            uint32_t afr[4];
            {
                float g0 = sB2[cA],     g1 = sB2[cA + 1];
                float g2 = sB2[cA + 8], g3 = sB2[cA + 9];
                CVT_BF16X2(afr[0], fmaxf(c0v[0] + g0, 0.f), fmaxf(c0v[1] + g1, 0.f));
                CVT_BF16X2(afr[1], fmaxf(c0v[2] + g0, 0.f), fmaxf(c0v[3] + g1, 0.f));
                CVT_BF16X2(afr[2], fmaxf(c1v[0] + g2, 0.f), fmaxf(c1v[1] + g3, 0.f));
                CVT_BF16X2(afr[3], fmaxf(c1v[2] + g2, 0.f), fmaxf(c1v[3] + g3, 0.f));
            }
            const int kloc = kb * 16 - c0;
            #pragma unroll
            for (int p = 0; p < 6; p++) {
                uint32_t bb[4];
                ldmB4(bb, addrB4(w3b, lane, p * 16, kloc, P_W3));
                mma16816(acc[2 * p],     afr, bb[0], bb[1]);
                mma16816(acc[2 * p + 1], afr, bb[2], bb[3]);
            }
            {
                uint32_t b0, b1v;
                ldmB2(b0, b1v, addrB2(w3b, lane, 96, kloc, P_W3));
                mma16816(acc[12], afr, b0, b1v);
            }
        }
    }

    // ---- layer 4 directly from fragments + quad shuffle reduce + MSE ----
    float psA[6] = {0.f, 0.f, 0.f, 0.f, 0.f, 0.f};
    float psB[6] = {0.f, 0.f, 0.f, 0.f, 0.f, 0.f};
    const int q = lane & 3;
    #pragma unroll
    for (int nt = 0; nt < 13; nt++) {
        int c = nt * 8 + 2 * q;
        if (c < 100) {
            float h0A = fmaxf(acc[nt][0] + sB3[c],     0.f);
            float h1A = fmaxf(acc[nt][1] + sB3[c + 1], 0.f);
            float h0B = fmaxf(acc[nt][2] + sB3[c],     0.f);
            float h1B = fmaxf(acc[nt][3] + sB3[c + 1], 0.f);
            #pragma unroll
            for (int c6 = 0; c6 < 6; c6++) {
                float w0 = sW4[c * 6 + c6], w1 = sW4[(c + 1) * 6 + c6];
                psA[c6] = fmaf(h0A, w0, fmaf(h1A, w1, psA[c6]));
                psB[c6] = fmaf(h0B, w0, fmaf(h1B, w1, psB[c6]));
            }
        }
    }
    #pragma unroll
    for (int off = 1; off <= 2; off <<= 1)
        #pragma unroll
        for (int c6 = 0; c6 < 6; c6++) {
            psA[c6] += __shfl_xor_sync(0xffffffffu, psA[c6], off);
            psB[c6] += __shfl_xor_sync(0xffffffffu, psB[c6], off);
        }
    float local = 0.f;
    if (q == 0) {
        int rA = m0 + (lane >> 2), rB = rA + 8;
        #pragma unroll
        for (int c6 = 0; c6 < 6; c6++) {
            if (rA < nrows) { float d = psA[c6] + sB4[c6] - sD[rA * 6 + c6]; local += d * d; }
            if (rB < nrows) { float d = psB[c6] + sB4[c6] - sD[rB * 6 + c6]; local += d * d; }
        }
    }
    #pragma unroll
    for (int off = 16; off; off >>= 1) local += __shfl_xor_sync(0xffffffffu, local, off);
    if (lane == 0) sRed[wid] = local;
    __syncthreads();
    if (tid == 0) {
        float s = 0.f;
        #pragma unroll
        for (int i = 0; i < 16; i++) s += sRed[i];
        atomicAdd(&g_acc, (double)s);
    }
}

__global__ void k_fin(float* out, int n) {
    double acc = g_acc;
    float v = (float)(acc / ((double)NROWS * 6.0));
    for (int i = threadIdx.x; i < n; i += blockDim.x) out[i] = v;
    __syncthreads();
    if (threadIdx.x < NA) g_cnt[threadIdx.x] = 0;
    if (threadIdx.x == NA) g_acc = 0.0;
}

extern "C" void kernel_launch(void* const* d_in, const int* in_sizes, int n_in,
                              void* d_out, int out_size) {
    const float* x  = (const float*)d_in[0];
    const float* nx = (const float*)d_in[1];
    const int*   ac = (const int*)d_in[2];
    const float* W1 = (const float*)d_in[3];
    const float* b1 = (const float*)d_in[4];
    const float* W2 = (const float*)d_in[5];
    const float* b2 = (const float*)d_in[6];
    const float* W3 = (const float*)d_in[7];
    const float* b3 = (const float*)d_in[8];
    const float* W4 = (const float*)d_in[9];
    const float* b4 = (const float*)d_in[10];

    cudaFuncSetAttribute(k_mlp, cudaFuncAttributeMaxDynamicSharedMemorySize, (int)SMEM_REQ);

    k_prep<<<PREP_BLKS + WPREP_BLKS, PTHR1>>>(x, nx, ac, W2, W3);
    k_mlp<<<NA * NT, NTHR, SMEM_REQ>>>(W1, b1, b2, b3, W4, b4);
    k_fin<<<1, 64>>>((float*)d_out, out_size);
}